// round 12
// baseline (speedup 1.0000x reference)
#include <cuda_runtime.h>
#include <math.h>

// ---------------------------------------------------------------------------
// MultiScaleAdaptiveElasticityLossWithLame
//   d_in[0]: deformation_field (2,3,160,192,160) f32
//   d_in[1]: image             (2,1,160,192,160) f32
//   out: scalar f32 loss
// ---------------------------------------------------------------------------

#define D0 160
#define H0 192
#define W0 160
#define D1 80
#define H1 96
#define W1 80
#define D2 40
#define H2 48
#define W2 40

#define VOL0 (D0*H0*W0)
#define VOL1 (D1*H1*W1)
#define VOL2 (D2*H2*W2)

__device__ float g_def1[2*3*VOL1];
__device__ float g_img1[2*1*VOL1];
__device__ float g_def2[2*3*VOL2];
__device__ float g_img2[2*1*VOL2];
__device__ double g_acc[3];    // zero-initialized at load; re-zeroed by finalize

// ---------------------------------------------------------------------------
// Fused trilinear downsample (align_corners=True): def (6 planes) + img (2).
// One output per thread; index decomposition entirely from grid/block dims.
template<int Di, int Hi, int Wi, int Do, int Ho, int Wo>
__global__ void downsample_both(const float* __restrict__ def,
                                const float* __restrict__ img,
                                float* __restrict__ odef,
                                float* __restrict__ oimg,
                                float rD, float rH, float rW)
{
    constexpr int OVOL = Do * Ho * Wo;
    constexpr int IVOL = Di * Hi * Wi;

    int x = threadIdx.x;
    int y = blockIdx.x * blockDim.y + threadIdx.y;
    int z = blockIdx.y;
    int p = blockIdx.z;            // 0..7

    const float* in; float* outp;
    if (p < 6) { in = def + p * IVOL;       outp = odef + p * OVOL; }
    else       { in = img + (p - 6) * IVOL; outp = oimg + (p - 6) * OVOL; }

    float cz = (float)z * rD;
    float cy = (float)y * rH;
    float cx = (float)x * rW;
    int z0 = min((int)floorf(cz), Di - 1);
    int y0 = min((int)floorf(cy), Hi - 1);
    int x0 = min((int)floorf(cx), Wi - 1);
    float wz = cz - (float)z0;
    float wy = cy - (float)y0;
    float wx = cx - (float)x0;
    int z1 = min(z0 + 1, Di - 1);
    int y1 = min(y0 + 1, Hi - 1);
    int x1 = min(x0 + 1, Wi - 1);

    const float* pz0 = in + z0 * (Hi * Wi);
    const float* pz1 = in + z1 * (Hi * Wi);
    int oy0 = y0 * Wi, oy1 = y1 * Wi;

    float v000 = __ldg(pz0 + oy0 + x0), v001 = __ldg(pz0 + oy0 + x1);
    float v010 = __ldg(pz0 + oy1 + x0), v011 = __ldg(pz0 + oy1 + x1);
    float v100 = __ldg(pz1 + oy0 + x0), v101 = __ldg(pz1 + oy0 + x1);
    float v110 = __ldg(pz1 + oy1 + x0), v111 = __ldg(pz1 + oy1 + x1);

    float a00 = v000 * (1.f - wx) + v001 * wx;
    float a01 = v010 * (1.f - wx) + v011 * wx;
    float a10 = v100 * (1.f - wx) + v101 * wx;
    float a11 = v110 * (1.f - wx) + v111 * wx;
    float b0 = a00 * (1.f - wy) + a01 * wy;
    float b1 = a10 * (1.f - wy) + a11 * wy;
    outp[z * (Ho * Wo) + y * Wo + x] = b0 * (1.f - wz) + b1 * wz;
}

// ---------------------------------------------------------------------------
// torch.gradient of one field at 4 consecutive W positions (R9-proven).
template<int D, int H, int W>
__device__ __forceinline__ void field_grads(const float* __restrict__ f,
                                            int d, int h, int w,
                                            float4& gD, float4& gH, float4& gW_)
{
    constexpr int sH = W;
    constexpr int sD = H * W;
    const float* base = f + d * sD + h * sH + w;

    float4 c = __ldg(reinterpret_cast<const float4*>(base));

    float xl = (w > 0)     ? __ldg(base - 1) : 0.f;
    float xr = (w + 4 < W) ? __ldg(base + 4) : 0.f;
    gW_.x = (w == 0)     ? (c.y - c.x) : 0.5f * (c.y - xl);
    gW_.y = 0.5f * (c.z - c.x);
    gW_.z = 0.5f * (c.w - c.y);
    gW_.w = (w + 4 == W) ? (c.w - c.z) : 0.5f * (xr - c.z);

    float4 hm = __ldg(reinterpret_cast<const float4*>(base - (h > 0     ? sH : 0)));
    float4 hp = __ldg(reinterpret_cast<const float4*>(base + (h < H - 1 ? sH : 0)));
    float sh = (h == 0 || h == H - 1) ? 1.0f : 0.5f;
    gH.x = sh * (hp.x - hm.x); gH.y = sh * (hp.y - hm.y);
    gH.z = sh * (hp.z - hm.z); gH.w = sh * (hp.w - hm.w);

    float4 dm = __ldg(reinterpret_cast<const float4*>(base - (d > 0     ? sD : 0)));
    float4 dp = __ldg(reinterpret_cast<const float4*>(base + (d < D - 1 ? sD : 0)));
    float sd = (d == 0 || d == D - 1) ? 1.0f : 0.5f;
    gD.x = sd * (dp.x - dm.x); gD.y = sd * (dp.y - dm.y);
    gD.z = sd * (dp.z - dm.z); gD.w = sd * (dp.w - dm.w);
}

__device__ __forceinline__ float4 f4add(float4 a, float4 b) {
    return make_float4(a.x + b.x, a.y + b.y, a.z + b.z, a.w + b.w);
}

// ---------------------------------------------------------------------------
// Flat energy kernel (R9-proven). Declares extern smem so scale 0 can be
// launched with a 64KB dynamic-smem footprint that caps residency at
// 3 blocks/SM, leaving registers free for downsample blocks to co-reside.
template<int D, int H, int W>
__global__ void __launch_bounds__(256)
energy_flat(const float* __restrict__ def, const float* __restrict__ img,
            int scale_idx)
{
    extern __shared__ float s_unused[];   // residency-cap only
    constexpr int Wq = W >> 2;
    constexpr int TOTAL = 2 * D * H * Wq;
    constexpr int VOL = D * H * W;
    int i = blockIdx.x * 256 + threadIdx.x;

    float local = 0.f;
    if (i < TOTAL) {
        int xq = i % Wq; int t = i / Wq;
        int h = t % H;   t /= H;
        int d = t % D;
        int n = t / D;
        int w = xq << 2;

        const float* base = def + n * 3 * VOL;

        float4 Exx, Eyy, Ezz, Sxy, Sxz, Syz;   // Sab = 2*Eab
        {
            float4 gD, gH, gW;
            field_grads<D, H, W>(base, d, h, w, gD, gH, gW);   // u
            Exx = gD; Sxy = gH; Sxz = gW;
        }
        {
            float4 gD, gH, gW;
            field_grads<D, H, W>(base + VOL, d, h, w, gD, gH, gW);   // v
            Eyy = gH; Sxy = f4add(Sxy, gD); Syz = gW;
        }
        {
            float4 gD, gH, gW;
            field_grads<D, H, W>(base + 2 * VOL, d, h, w, gD, gH, gW);   // w
            Ezz = gW; Sxz = f4add(Sxz, gD); Syz = f4add(Syz, gH);
        }
        float4 g2;
        {
            float4 gD, gH, gW;
            field_grads<D, H, W>(img + n * VOL, d, h, w, gD, gH, gW);
            g2.x = gD.x * gD.x + gH.x * gH.x + gW.x * gW.x;
            g2.y = gD.y * gD.y + gH.y * gH.y + gW.y * gW.y;
            g2.z = gD.z * gD.z + gH.z * gH.z + gW.z * gW.z;
            g2.w = gD.w * gD.w + gH.w * gH.w + gW.w * gW.w;
        }

        const float* exx = reinterpret_cast<const float*>(&Exx);
        const float* eyy = reinterpret_cast<const float*>(&Eyy);
        const float* ezz = reinterpret_cast<const float*>(&Ezz);
        const float* sxy = reinterpret_cast<const float*>(&Sxy);
        const float* sxz = reinterpret_cast<const float*>(&Sxz);
        const float* syz = reinterpret_cast<const float*>(&Syz);
        const float* gg  = reinterpret_cast<const float*>(&g2);

        #pragma unroll
        for (int j = 0; j < 4; j++) {
            float exy = 0.5f * sxy[j];
            float exz = 0.5f * sxz[j];
            float eyz = 0.5f * syz[j];
            float tr = exx[j] + eyy[j] + ezz[j];
            float g = sqrtf(gg[j]);
            float lam = 1.0f + 0.5f * g;
            float mu  = 1.0f + 0.5f * g;
            float e = 0.5f * lam * tr * tr
                    + mu * (exx[j] * exx[j] + eyy[j] * eyy[j] + ezz[j] * ezz[j]
                            + 2.0f * (exy * exy + exz * exz + eyz * eyz));
            local += (1.0f + 0.1f * g) * e;
        }
    }

    #pragma unroll
    for (int o = 16; o > 0; o >>= 1)
        local += __shfl_down_sync(0xffffffffu, local, o);

    __shared__ float ws[8];
    int lane = threadIdx.x & 31;
    int wid  = threadIdx.x >> 5;
    if (lane == 0) ws[wid] = local;
    __syncthreads();
    if (wid == 0) {
        float s = (lane < 8) ? ws[lane] : 0.f;
        #pragma unroll
        for (int o = 4; o > 0; o >>= 1)
            s += __shfl_down_sync(0xffffffffu, s, o);
        if (lane == 0)
            atomicAdd(&g_acc[scale_idx], (double)s);
    }
}

// ---------------------------------------------------------------------------
// Finalize: read accumulators, write the loss, re-zero for the next replay
// (graph replays are stream-ordered, so this is deterministic).
__global__ void finalize_kernel(float* out) {
    double m0 = g_acc[0] / (2.0 * VOL0);
    double m1 = g_acc[1] / (2.0 * VOL1);
    double m2 = g_acc[2] / (2.0 * VOL2);
    out[0] = (float)(m0 + m1 + m2);
    g_acc[0] = 0.0; g_acc[1] = 0.0; g_acc[2] = 0.0;
}

// ---------------------------------------------------------------------------
extern "C" void kernel_launch(void* const* d_in, const int* in_sizes, int n_in,
                              void* d_out, int out_size)
{
    const float* def = (const float*)d_in[0];
    const float* img = (const float*)d_in[1];
    float* out = (float*)d_out;

    float *p_def1, *p_img1, *p_def2, *p_img2;
    cudaGetSymbolAddress((void**)&p_def1, g_def1);
    cudaGetSymbolAddress((void**)&p_img1, g_img1);
    cudaGetSymbolAddress((void**)&p_def2, g_def2);
    cudaGetSymbolAddress((void**)&p_img2, g_img2);

    // One-time resource setup (first call is the uncaptured correctness run).
    static cudaStream_t s_side = nullptr;
    static cudaEvent_t  s_fork = nullptr, s_join = nullptr;
    constexpr int E0_SMEM = 64 * 1024;   // caps e0 at 3 blocks/SM (228KB/64KB)
    if (s_side == nullptr) {
        cudaStreamCreateWithFlags(&s_side, cudaStreamNonBlocking);
        cudaEventCreateWithFlags(&s_fork, cudaEventDisableTiming);
        cudaEventCreateWithFlags(&s_join, cudaEventDisableTiming);
        cudaFuncSetAttribute(energy_flat<D0, H0, W0>,
                             cudaFuncAttributeMaxDynamicSharedMemorySize, E0_SMEM);
    }

    // Fork side stream (independent of e0; both start at t0).
    cudaEventRecord(s_fork, 0);
    cudaStreamWaitEvent(s_side, s_fork, 0);

    // ---- main stream: scale 0 energy, residency-capped ----
    {
        constexpr int T0 = 2 * D0 * H0 * (W0 / 4);
        energy_flat<D0, H0, W0><<<(T0 + 255) / 256, 256, E0_SMEM>>>(def, img, 0);
    }

    // ---- side stream: scale 1 then scale 2 (backfills SMs beside e0) ----
    {
        float rD = (float)((double)(D0 - 1) / (double)(D1 - 1));
        float rH = (float)((double)(H0 - 1) / (double)(H1 - 1));
        float rW = (float)((double)(W0 - 1) / (double)(W1 - 1));
        dim3 blk(W1, 3);
        dim3 grd(H1 / 3, D1, 8);
        downsample_both<D0, H0, W0, D1, H1, W1>
            <<<grd, blk, 0, s_side>>>(def, img, p_def1, p_img1, rD, rH, rW);

        constexpr int T1 = 2 * D1 * H1 * (W1 / 4);
        energy_flat<D1, H1, W1><<<(T1 + 255) / 256, 256, 0, s_side>>>(p_def1, p_img1, 1);
    }
    {
        float rD = (float)((double)(D0 - 1) / (double)(D2 - 1));
        float rH = (float)((double)(H0 - 1) / (double)(H2 - 1));
        float rW = (float)((double)(W0 - 1) / (double)(W2 - 1));
        dim3 blk(W2, 6);
        dim3 grd(H2 / 6, D2, 8);
        downsample_both<D0, H0, W0, D2, H2, W2>
            <<<grd, blk, 0, s_side>>>(def, img, p_def2, p_img2, rD, rH, rW);

        constexpr int T2 = 2 * D2 * H2 * (W2 / 4);
        energy_flat<D2, H2, W2><<<(T2 + 255) / 256, 256, 0, s_side>>>(p_def2, p_img2, 2);
    }

    // Join, then finalize (also re-zeroes accumulators for the next replay).
    cudaEventRecord(s_join, s_side);
    cudaStreamWaitEvent(0, s_join, 0);
    finalize_kernel<<<1, 1>>>(out);
}

// round 13
// speedup vs baseline: 1.0506x; 1.0506x over previous
#include <cuda_runtime.h>
#include <math.h>

// ---------------------------------------------------------------------------
// MultiScaleAdaptiveElasticityLossWithLame
//   d_in[0]: deformation_field (2,3,160,192,160) f32
//   d_in[1]: image             (2,1,160,192,160) f32
//   out: scalar f32 loss
// ---------------------------------------------------------------------------

#define D0 160
#define H0 192
#define W0 160
#define D1 80
#define H1 96
#define W1 80
#define D2 40
#define H2 48
#define W2 40

#define VOL0 (D0*H0*W0)
#define VOL1 (D1*H1*W1)
#define VOL2 (D2*H2*W2)

__device__ float g_def1[2*3*VOL1];
__device__ float g_img1[2*1*VOL1];
__device__ float g_def2[2*3*VOL2];
__device__ float g_img2[2*1*VOL2];
__device__ double g_acc[3];    // zeroed at load; re-zeroed by finalize each replay

// ---------------------------------------------------------------------------
// Fused trilinear downsample (align_corners=True): def (6 planes) + img (2).
// One output per thread; index decomposition entirely from grid/block dims.
template<int Di, int Hi, int Wi, int Do, int Ho, int Wo>
__global__ void downsample_both(const float* __restrict__ def,
                                const float* __restrict__ img,
                                float* __restrict__ odef,
                                float* __restrict__ oimg,
                                float rD, float rH, float rW)
{
    constexpr int OVOL = Do * Ho * Wo;
    constexpr int IVOL = Di * Hi * Wi;

    int x = threadIdx.x;
    int y = blockIdx.x * blockDim.y + threadIdx.y;
    int z = blockIdx.y;
    int p = blockIdx.z;            // 0..7

    const float* in; float* outp;
    if (p < 6) { in = def + p * IVOL;       outp = odef + p * OVOL; }
    else       { in = img + (p - 6) * IVOL; outp = oimg + (p - 6) * OVOL; }

    float cz = (float)z * rD;
    float cy = (float)y * rH;
    float cx = (float)x * rW;
    int z0 = min((int)floorf(cz), Di - 1);
    int y0 = min((int)floorf(cy), Hi - 1);
    int x0 = min((int)floorf(cx), Wi - 1);
    float wz = cz - (float)z0;
    float wy = cy - (float)y0;
    float wx = cx - (float)x0;
    int z1 = min(z0 + 1, Di - 1);
    int y1 = min(y0 + 1, Hi - 1);
    int x1 = min(x0 + 1, Wi - 1);

    const float* pz0 = in + z0 * (Hi * Wi);
    const float* pz1 = in + z1 * (Hi * Wi);
    int oy0 = y0 * Wi, oy1 = y1 * Wi;

    float v000 = __ldg(pz0 + oy0 + x0), v001 = __ldg(pz0 + oy0 + x1);
    float v010 = __ldg(pz0 + oy1 + x0), v011 = __ldg(pz0 + oy1 + x1);
    float v100 = __ldg(pz1 + oy0 + x0), v101 = __ldg(pz1 + oy0 + x1);
    float v110 = __ldg(pz1 + oy1 + x0), v111 = __ldg(pz1 + oy1 + x1);

    float a00 = v000 * (1.f - wx) + v001 * wx;
    float a01 = v010 * (1.f - wx) + v011 * wx;
    float a10 = v100 * (1.f - wx) + v101 * wx;
    float a11 = v110 * (1.f - wx) + v111 * wx;
    float b0 = a00 * (1.f - wy) + a01 * wy;
    float b1 = a10 * (1.f - wy) + a11 * wy;
    outp[z * (Ho * Wo) + y * Wo + x] = b0 * (1.f - wz) + b1 * wz;
}

// ---------------------------------------------------------------------------
// torch.gradient of one field at 4 consecutive W positions.
// W-halo (xl = w-1, xr = w+4) comes from neighbor lanes via shuffle:
// consecutive lanes hold consecutive quads, so lane-1's c.w == our w-1 and
// lane+1's c.x == our w+4. Warp-edge lanes with interior xq fall back to a
// predicated 1-lane scalar load. Row-wrap lanes use the one-sided edge
// formula, so their (garbage) shuffled value is never consumed.
template<int D, int H, int W>
__device__ __forceinline__ void field_grads(const float* __restrict__ f,
                                            int d, int h, int w, int lane,
                                            float4& gD, float4& gH, float4& gW_)
{
    constexpr int sH = W;
    constexpr int sD = H * W;
    const float* base = f + d * sD + h * sH + w;

    float4 c = __ldg(reinterpret_cast<const float4*>(base));

    float xl = __shfl_up_sync(0xffffffffu, c.w, 1);
    float xr = __shfl_down_sync(0xffffffffu, c.x, 1);
    if (lane == 0  && w > 0)     xl = __ldg(base - 1);
    if (lane == 31 && w + 4 < W) xr = __ldg(base + 4);

    gW_.x = (w == 0)     ? (c.y - c.x) : 0.5f * (c.y - xl);
    gW_.y = 0.5f * (c.z - c.x);
    gW_.z = 0.5f * (c.w - c.y);
    gW_.w = (w + 4 == W) ? (c.w - c.z) : 0.5f * (xr - c.z);

    float4 hm = __ldg(reinterpret_cast<const float4*>(base - (h > 0     ? sH : 0)));
    float4 hp = __ldg(reinterpret_cast<const float4*>(base + (h < H - 1 ? sH : 0)));
    float sh = (h == 0 || h == H - 1) ? 1.0f : 0.5f;
    gH.x = sh * (hp.x - hm.x); gH.y = sh * (hp.y - hm.y);
    gH.z = sh * (hp.z - hm.z); gH.w = sh * (hp.w - hm.w);

    float4 dm = __ldg(reinterpret_cast<const float4*>(base - (d > 0     ? sD : 0)));
    float4 dp = __ldg(reinterpret_cast<const float4*>(base + (d < D - 1 ? sD : 0)));
    float sd = (d == 0 || d == D - 1) ? 1.0f : 0.5f;
    gD.x = sd * (dp.x - dm.x); gD.y = sd * (dp.y - dm.y);
    gD.z = sd * (dp.z - dm.z); gD.w = sd * (dp.w - dm.w);
}

__device__ __forceinline__ float4 f4add(float4 a, float4 b) {
    return make_float4(a.x + b.x, a.y + b.y, a.z + b.z, a.w + b.w);
}

// ---------------------------------------------------------------------------
// Flat energy kernel (R9 structure + shuffle W-halo). NOTE: every scale's
// TOTAL is an exact multiple of 256, so warps never diverge at the guard and
// full-mask shuffles are safe.
template<int D, int H, int W>
__global__ void __launch_bounds__(256)
energy_flat(const float* __restrict__ def, const float* __restrict__ img,
            int scale_idx)
{
    constexpr int Wq = W >> 2;
    constexpr int TOTAL = 2 * D * H * Wq;
    constexpr int VOL = D * H * W;
    int i = blockIdx.x * 256 + threadIdx.x;
    int lane = threadIdx.x & 31;

    float local = 0.f;
    if (i < TOTAL) {
        int xq = i % Wq; int t = i / Wq;
        int h = t % H;   t /= H;
        int d = t % D;
        int n = t / D;
        int w = xq << 2;

        const float* base = def + n * 3 * VOL;

        float4 Exx, Eyy, Ezz, Sxy, Sxz, Syz;   // Sab = 2*Eab
        {
            float4 gD, gH, gW;
            field_grads<D, H, W>(base, d, h, w, lane, gD, gH, gW);   // u
            Exx = gD; Sxy = gH; Sxz = gW;
        }
        {
            float4 gD, gH, gW;
            field_grads<D, H, W>(base + VOL, d, h, w, lane, gD, gH, gW);   // v
            Eyy = gH; Sxy = f4add(Sxy, gD); Syz = gW;
        }
        {
            float4 gD, gH, gW;
            field_grads<D, H, W>(base + 2 * VOL, d, h, w, lane, gD, gH, gW);   // w
            Ezz = gW; Sxz = f4add(Sxz, gD); Syz = f4add(Syz, gH);
        }
        float4 g2;
        {
            float4 gD, gH, gW;
            field_grads<D, H, W>(img + n * VOL, d, h, w, lane, gD, gH, gW);
            g2.x = gD.x * gD.x + gH.x * gH.x + gW.x * gW.x;
            g2.y = gD.y * gD.y + gH.y * gH.y + gW.y * gW.y;
            g2.z = gD.z * gD.z + gH.z * gH.z + gW.z * gW.z;
            g2.w = gD.w * gD.w + gH.w * gH.w + gW.w * gW.w;
        }

        const float* exx = reinterpret_cast<const float*>(&Exx);
        const float* eyy = reinterpret_cast<const float*>(&Eyy);
        const float* ezz = reinterpret_cast<const float*>(&Ezz);
        const float* sxy = reinterpret_cast<const float*>(&Sxy);
        const float* sxz = reinterpret_cast<const float*>(&Sxz);
        const float* syz = reinterpret_cast<const float*>(&Syz);
        const float* gg  = reinterpret_cast<const float*>(&g2);

        #pragma unroll
        for (int j = 0; j < 4; j++) {
            float exy = 0.5f * sxy[j];
            float exz = 0.5f * sxz[j];
            float eyz = 0.5f * syz[j];
            float tr = exx[j] + eyy[j] + ezz[j];
            float g = sqrtf(gg[j]);
            float lam = 1.0f + 0.5f * g;
            float mu  = 1.0f + 0.5f * g;
            float e = 0.5f * lam * tr * tr
                    + mu * (exx[j] * exx[j] + eyy[j] * eyy[j] + ezz[j] * ezz[j]
                            + 2.0f * (exy * exy + exz * exz + eyz * eyz));
            local += (1.0f + 0.1f * g) * e;
        }
    }

    #pragma unroll
    for (int o = 16; o > 0; o >>= 1)
        local += __shfl_down_sync(0xffffffffu, local, o);

    __shared__ float ws[8];
    int wid = threadIdx.x >> 5;
    if (lane == 0) ws[wid] = local;
    __syncthreads();
    if (wid == 0) {
        float s = (lane < 8) ? ws[lane] : 0.f;
        #pragma unroll
        for (int o = 4; o > 0; o >>= 1)
            s += __shfl_down_sync(0xffffffffu, s, o);
        if (lane == 0)
            atomicAdd(&g_acc[scale_idx], (double)s);
    }
}

// ---------------------------------------------------------------------------
// Finalize: emit loss, then re-zero accumulators for the next replay
// (stream-ordered -> deterministic).
__global__ void finalize_kernel(float* out) {
    double m0 = g_acc[0] / (2.0 * VOL0);
    double m1 = g_acc[1] / (2.0 * VOL1);
    double m2 = g_acc[2] / (2.0 * VOL2);
    out[0] = (float)(m0 + m1 + m2);
    g_acc[0] = 0.0; g_acc[1] = 0.0; g_acc[2] = 0.0;
}

// ---------------------------------------------------------------------------
extern "C" void kernel_launch(void* const* d_in, const int* in_sizes, int n_in,
                              void* d_out, int out_size)
{
    const float* def = (const float*)d_in[0];
    const float* img = (const float*)d_in[1];
    float* out = (float*)d_out;

    float *p_def1, *p_img1, *p_def2, *p_img2;
    cudaGetSymbolAddress((void**)&p_def1, g_def1);
    cudaGetSymbolAddress((void**)&p_img1, g_img1);
    cudaGetSymbolAddress((void**)&p_def2, g_def2);
    cudaGetSymbolAddress((void**)&p_img2, g_img2);

    // Side stream + events, created once on the (uncaptured) correctness call.
    static cudaStream_t s_side = nullptr;
    static cudaEvent_t  s_fork = nullptr, s_join = nullptr;
    if (s_side == nullptr) {
        cudaStreamCreateWithFlags(&s_side, cudaStreamNonBlocking);
        cudaEventCreateWithFlags(&s_fork, cudaEventDisableTiming);
        cudaEventCreateWithFlags(&s_join, cudaEventDisableTiming);
    }

    // Fork: scales 1 & 2 on the side stream, concurrent with scale 0.
    cudaEventRecord(s_fork, 0);
    cudaStreamWaitEvent(s_side, s_fork, 0);

    // ---- side stream: scale 1 then scale 2 ----
    {
        float rD = (float)((double)(D0 - 1) / (double)(D1 - 1));
        float rH = (float)((double)(H0 - 1) / (double)(H1 - 1));
        float rW = (float)((double)(W0 - 1) / (double)(W1 - 1));
        dim3 blk(W1, 3);
        dim3 grd(H1 / 3, D1, 8);
        downsample_both<D0, H0, W0, D1, H1, W1>
            <<<grd, blk, 0, s_side>>>(def, img, p_def1, p_img1, rD, rH, rW);

        constexpr int T1 = 2 * D1 * H1 * (W1 / 4);
        energy_flat<D1, H1, W1><<<(T1 + 255) / 256, 256, 0, s_side>>>(p_def1, p_img1, 1);
    }
    {
        float rD = (float)((double)(D0 - 1) / (double)(D2 - 1));
        float rH = (float)((double)(H0 - 1) / (double)(H2 - 1));
        float rW = (float)((double)(W0 - 1) / (double)(W2 - 1));
        dim3 blk(W2, 6);
        dim3 grd(H2 / 6, D2, 8);
        downsample_both<D0, H0, W0, D2, H2, W2>
            <<<grd, blk, 0, s_side>>>(def, img, p_def2, p_img2, rD, rH, rW);

        constexpr int T2 = 2 * D2 * H2 * (W2 / 4);
        energy_flat<D2, H2, W2><<<(T2 + 255) / 256, 256, 0, s_side>>>(p_def2, p_img2, 2);
    }

    // ---- main stream: scale 0 ----
    {
        constexpr int T0 = 2 * D0 * H0 * (W0 / 4);
        energy_flat<D0, H0, W0><<<(T0 + 255) / 256, 256>>>(def, img, 0);
    }

    // Join, then finalize.
    cudaEventRecord(s_join, s_side);
    cudaStreamWaitEvent(0, s_join, 0);
    finalize_kernel<<<1, 1>>>(out);
}

// round 14
// speedup vs baseline: 1.1909x; 1.1335x over previous
#include <cuda_runtime.h>
#include <math.h>

// ---------------------------------------------------------------------------
// MultiScaleAdaptiveElasticityLossWithLame
//   d_in[0]: deformation_field (2,3,160,192,160) f32
//   d_in[1]: image             (2,1,160,192,160) f32
//   out: scalar f32 loss
// ---------------------------------------------------------------------------

#define D0 160
#define H0 192
#define W0 160
#define D1 80
#define H1 96
#define W1 80
#define D2 40
#define H2 48
#define W2 40

#define VOL0 (D0*H0*W0)
#define VOL1 (D1*H1*W1)
#define VOL2 (D2*H2*W2)

__device__ float g_def1[2*3*VOL1];
__device__ float g_img1[2*1*VOL1];
__device__ float g_def2[2*3*VOL2];
__device__ float g_img2[2*1*VOL2];
__device__ double g_acc[3];    // zeroed at load; re-zeroed by finalize each replay

// ---------------------------------------------------------------------------
// Fused trilinear downsample (align_corners=True): def (6 planes) + img (2).
// One output per thread; index decomposition entirely from grid/block dims.
template<int Di, int Hi, int Wi, int Do, int Ho, int Wo>
__global__ void downsample_both(const float* __restrict__ def,
                                const float* __restrict__ img,
                                float* __restrict__ odef,
                                float* __restrict__ oimg,
                                float rD, float rH, float rW)
{
    constexpr int OVOL = Do * Ho * Wo;
    constexpr int IVOL = Di * Hi * Wi;

    int x = threadIdx.x;
    int y = blockIdx.x * blockDim.y + threadIdx.y;
    int z = blockIdx.y;
    int p = blockIdx.z;            // 0..7

    const float* in; float* outp;
    if (p < 6) { in = def + p * IVOL;       outp = odef + p * OVOL; }
    else       { in = img + (p - 6) * IVOL; outp = oimg + (p - 6) * OVOL; }

    float cz = (float)z * rD;
    float cy = (float)y * rH;
    float cx = (float)x * rW;
    int z0 = min((int)floorf(cz), Di - 1);
    int y0 = min((int)floorf(cy), Hi - 1);
    int x0 = min((int)floorf(cx), Wi - 1);
    float wz = cz - (float)z0;
    float wy = cy - (float)y0;
    float wx = cx - (float)x0;
    int z1 = min(z0 + 1, Di - 1);
    int y1 = min(y0 + 1, Hi - 1);
    int x1 = min(x0 + 1, Wi - 1);

    const float* pz0 = in + z0 * (Hi * Wi);
    const float* pz1 = in + z1 * (Hi * Wi);
    int oy0 = y0 * Wi, oy1 = y1 * Wi;

    float v000 = __ldg(pz0 + oy0 + x0), v001 = __ldg(pz0 + oy0 + x1);
    float v010 = __ldg(pz0 + oy1 + x0), v011 = __ldg(pz0 + oy1 + x1);
    float v100 = __ldg(pz1 + oy0 + x0), v101 = __ldg(pz1 + oy0 + x1);
    float v110 = __ldg(pz1 + oy1 + x0), v111 = __ldg(pz1 + oy1 + x1);

    float a00 = v000 * (1.f - wx) + v001 * wx;
    float a01 = v010 * (1.f - wx) + v011 * wx;
    float a10 = v100 * (1.f - wx) + v101 * wx;
    float a11 = v110 * (1.f - wx) + v111 * wx;
    float b0 = a00 * (1.f - wy) + a01 * wy;
    float b1 = a10 * (1.f - wy) + a11 * wy;
    outp[z * (Ho * Wo) + y * Wo + x] = b0 * (1.f - wz) + b1 * wz;
}

// ---------------------------------------------------------------------------
// torch.gradient of one field at 4 consecutive W positions (R9-proven form).
template<int D, int H, int W>
__device__ __forceinline__ void field_grads(const float* __restrict__ f,
                                            int d, int h, int w,
                                            float4& gD, float4& gH, float4& gW_)
{
    constexpr int sH = W;
    constexpr int sD = H * W;
    const float* base = f + d * sD + h * sH + w;

    float4 c = __ldg(reinterpret_cast<const float4*>(base));

    float xl = (w > 0)     ? __ldg(base - 1) : 0.f;
    float xr = (w + 4 < W) ? __ldg(base + 4) : 0.f;
    gW_.x = (w == 0)     ? (c.y - c.x) : 0.5f * (c.y - xl);
    gW_.y = 0.5f * (c.z - c.x);
    gW_.z = 0.5f * (c.w - c.y);
    gW_.w = (w + 4 == W) ? (c.w - c.z) : 0.5f * (xr - c.z);

    float4 hm = __ldg(reinterpret_cast<const float4*>(base - (h > 0     ? sH : 0)));
    float4 hp = __ldg(reinterpret_cast<const float4*>(base + (h < H - 1 ? sH : 0)));
    float sh = (h == 0 || h == H - 1) ? 1.0f : 0.5f;
    gH.x = sh * (hp.x - hm.x); gH.y = sh * (hp.y - hm.y);
    gH.z = sh * (hp.z - hm.z); gH.w = sh * (hp.w - hm.w);

    float4 dm = __ldg(reinterpret_cast<const float4*>(base - (d > 0     ? sD : 0)));
    float4 dp = __ldg(reinterpret_cast<const float4*>(base + (d < D - 1 ? sD : 0)));
    float sd = (d == 0 || d == D - 1) ? 1.0f : 0.5f;
    gD.x = sd * (dp.x - dm.x); gD.y = sd * (dp.y - dm.y);
    gD.z = sd * (dp.z - dm.z); gD.w = sd * (dp.w - dm.w);
}

__device__ __forceinline__ float4 f4add(float4 a, float4 b) {
    return make_float4(a.x + b.x, a.y + b.y, a.z + b.z, a.w + b.w);
}

// ---------------------------------------------------------------------------
// Flat energy kernel (R9-proven, 64 regs).
template<int D, int H, int W>
__global__ void __launch_bounds__(256)
energy_flat(const float* __restrict__ def, const float* __restrict__ img,
            int scale_idx)
{
    constexpr int Wq = W >> 2;
    constexpr int TOTAL = 2 * D * H * Wq;
    constexpr int VOL = D * H * W;
    int i = blockIdx.x * 256 + threadIdx.x;

    float local = 0.f;
    if (i < TOTAL) {
        int xq = i % Wq; int t = i / Wq;
        int h = t % H;   t /= H;
        int d = t % D;
        int n = t / D;
        int w = xq << 2;

        const float* base = def + n * 3 * VOL;

        float4 Exx, Eyy, Ezz, Sxy, Sxz, Syz;   // Sab = 2*Eab
        {
            float4 gD, gH, gW;
            field_grads<D, H, W>(base, d, h, w, gD, gH, gW);   // u
            Exx = gD; Sxy = gH; Sxz = gW;
        }
        {
            float4 gD, gH, gW;
            field_grads<D, H, W>(base + VOL, d, h, w, gD, gH, gW);   // v
            Eyy = gH; Sxy = f4add(Sxy, gD); Syz = gW;
        }
        {
            float4 gD, gH, gW;
            field_grads<D, H, W>(base + 2 * VOL, d, h, w, gD, gH, gW);   // w
            Ezz = gW; Sxz = f4add(Sxz, gD); Syz = f4add(Syz, gH);
        }
        float4 g2;
        {
            float4 gD, gH, gW;
            field_grads<D, H, W>(img + n * VOL, d, h, w, gD, gH, gW);
            g2.x = gD.x * gD.x + gH.x * gH.x + gW.x * gW.x;
            g2.y = gD.y * gD.y + gH.y * gH.y + gW.y * gW.y;
            g2.z = gD.z * gD.z + gH.z * gH.z + gW.z * gW.z;
            g2.w = gD.w * gD.w + gH.w * gH.w + gW.w * gW.w;
        }

        const float* exx = reinterpret_cast<const float*>(&Exx);
        const float* eyy = reinterpret_cast<const float*>(&Eyy);
        const float* ezz = reinterpret_cast<const float*>(&Ezz);
        const float* sxy = reinterpret_cast<const float*>(&Sxy);
        const float* sxz = reinterpret_cast<const float*>(&Sxz);
        const float* syz = reinterpret_cast<const float*>(&Syz);
        const float* gg  = reinterpret_cast<const float*>(&g2);

        #pragma unroll
        for (int j = 0; j < 4; j++) {
            float exy = 0.5f * sxy[j];
            float exz = 0.5f * sxz[j];
            float eyz = 0.5f * syz[j];
            float tr = exx[j] + eyy[j] + ezz[j];
            float g = sqrtf(gg[j]);
            float lam = 1.0f + 0.5f * g;
            float mu  = 1.0f + 0.5f * g;
            float e = 0.5f * lam * tr * tr
                    + mu * (exx[j] * exx[j] + eyy[j] * eyy[j] + ezz[j] * ezz[j]
                            + 2.0f * (exy * exy + exz * exz + eyz * eyz));
            local += (1.0f + 0.1f * g) * e;
        }
    }

    #pragma unroll
    for (int o = 16; o > 0; o >>= 1)
        local += __shfl_down_sync(0xffffffffu, local, o);

    __shared__ float ws[8];
    int lane = threadIdx.x & 31;
    int wid  = threadIdx.x >> 5;
    if (lane == 0) ws[wid] = local;
    __syncthreads();
    if (wid == 0) {
        float s = (lane < 8) ? ws[lane] : 0.f;
        #pragma unroll
        for (int o = 4; o > 0; o >>= 1)
            s += __shfl_down_sync(0xffffffffu, s, o);
        if (lane == 0)
            atomicAdd(&g_acc[scale_idx], (double)s);
    }
}

// ---------------------------------------------------------------------------
// Finalize: emit loss, then re-zero accumulators for the next replay.
__global__ void finalize_kernel(float* out) {
    double m0 = g_acc[0] / (2.0 * VOL0);
    double m1 = g_acc[1] / (2.0 * VOL1);
    double m2 = g_acc[2] / (2.0 * VOL2);
    out[0] = (float)(m0 + m1 + m2);
    g_acc[0] = 0.0; g_acc[1] = 0.0; g_acc[2] = 0.0;
}

// ---------------------------------------------------------------------------
extern "C" void kernel_launch(void* const* d_in, const int* in_sizes, int n_in,
                              void* d_out, int out_size)
{
    const float* def = (const float*)d_in[0];
    const float* img = (const float*)d_in[1];
    float* out = (float*)d_out;

    float *p_def1, *p_img1, *p_def2, *p_img2;
    cudaGetSymbolAddress((void**)&p_def1, g_def1);
    cudaGetSymbolAddress((void**)&p_img1, g_img1);
    cudaGetSymbolAddress((void**)&p_def2, g_def2);
    cudaGetSymbolAddress((void**)&p_img2, g_img2);

    // Streams/events, created once on the (uncaptured) correctness call.
    static cudaStream_t s_a = nullptr, s_b = nullptr;
    static cudaEvent_t  e_fork = nullptr, e_ja = nullptr, e_jb = nullptr;
    if (s_a == nullptr) {
        cudaStreamCreateWithFlags(&s_a, cudaStreamNonBlocking);
        cudaStreamCreateWithFlags(&s_b, cudaStreamNonBlocking);
        cudaEventCreateWithFlags(&e_fork, cudaEventDisableTiming);
        cudaEventCreateWithFlags(&e_ja,   cudaEventDisableTiming);
        cudaEventCreateWithFlags(&e_jb,   cudaEventDisableTiming);
    }

    // Fork both side streams off the main stream's current position.
    cudaEventRecord(e_fork, 0);
    cudaStreamWaitEvent(s_a, e_fork, 0);
    cudaStreamWaitEvent(s_b, e_fork, 0);

    // ---- main stream FIRST: scale 0 (the critical path) ----
    {
        constexpr int T0 = 2 * D0 * H0 * (W0 / 4);
        energy_flat<D0, H0, W0><<<(T0 + 255) / 256, 256>>>(def, img, 0);
    }

    // ---- side stream A: ds1 -> e1 ----
    {
        float rD = (float)((double)(D0 - 1) / (double)(D1 - 1));
        float rH = (float)((double)(H0 - 1) / (double)(H1 - 1));
        float rW = (float)((double)(W0 - 1) / (double)(W1 - 1));
        dim3 blk(W1, 3);
        dim3 grd(H1 / 3, D1, 8);
        downsample_both<D0, H0, W0, D1, H1, W1>
            <<<grd, blk, 0, s_a>>>(def, img, p_def1, p_img1, rD, rH, rW);

        constexpr int T1 = 2 * D1 * H1 * (W1 / 4);
        energy_flat<D1, H1, W1><<<(T1 + 255) / 256, 256, 0, s_a>>>(p_def1, p_img1, 1);
    }

    // ---- side stream B: ds2 -> e2 (independent of chain A) ----
    {
        float rD = (float)((double)(D0 - 1) / (double)(D2 - 1));
        float rH = (float)((double)(H0 - 1) / (double)(H2 - 1));
        float rW = (float)((double)(W0 - 1) / (double)(W2 - 1));
        dim3 blk(W2, 6);
        dim3 grd(H2 / 6, D2, 8);
        downsample_both<D0, H0, W0, D2, H2, W2>
            <<<grd, blk, 0, s_b>>>(def, img, p_def2, p_img2, rD, rH, rW);

        constexpr int T2 = 2 * D2 * H2 * (W2 / 4);
        energy_flat<D2, H2, W2><<<(T2 + 255) / 256, 256, 0, s_b>>>(p_def2, p_img2, 2);
    }

    // Join both side streams, then finalize.
    cudaEventRecord(e_ja, s_a);
    cudaEventRecord(e_jb, s_b);
    cudaStreamWaitEvent(0, e_ja, 0);
    cudaStreamWaitEvent(0, e_jb, 0);
    finalize_kernel<<<1, 1>>>(out);
}